// round 15
// baseline (speedup 1.0000x reference)
#include <cuda_runtime.h>
#include <cuda_fp16.h>
#include <cstdint>

// Problem constants
#define TOK    8192
#define EMB_   768
#define NQKV   2304
#define HDIM   96
#define SEQ    2048

// log2(e)/sqrt(768): folded into q so softmax is a bare ex2.approx
#define SCALE_Q 0.05205875899635608f

// ---------------- scratch (static device globals) ---------------------------
__device__ __half g_xh[TOK * EMB_];     // fp16 x
__device__ __half g_w1[NQKV * EMB_];    // permuted+transposed Wqkv  [N][K]
__device__ float  g_b1[NQKV];           // permuted bqkv (fp32)
__device__ __half g_w2[EMB_ * EMB_];    // transposed Wproj [N][K]
__device__ __half g_q[TOK * EMB_];      // [b][tok][h*96+d], pre-scaled
__device__ __half g_k[TOK * EMB_];      // [b][tok][h*96+d]
__device__ __half g_vt[TOK * EMB_];     // transposed: [b][h*96+d][tok]
__device__ __half g_ctx[TOK * EMB_];    // attention out, fp16

// ---------------- helpers ---------------------------------------------------
__device__ __forceinline__ float ex2f(float x) {
    float y;
    asm("ex2.approx.f32 %0, %1;" : "=f"(y) : "f"(x));
    return y;
}
__device__ __forceinline__ unsigned packh(float lo, float hi) {
    unsigned u;
    asm("cvt.rn.f16x2.f32 %0, %1, %2;" : "=r"(u) : "f"(hi), "f"(lo));
    return u;
}
__device__ __forceinline__ void cpa16(uint32_t dst, const void* src) {
    asm volatile("cp.async.cg.shared.global [%0], [%1], 16;" :: "r"(dst), "l"(src));
}
#define CP_COMMIT() asm volatile("cp.async.commit_group;")
#define CP_WAIT(n)  asm volatile("cp.async.wait_group %0;" :: "n"(n))

// D += A(16x16,row) * B(16x8,col), fp16 in / f32 acc
__device__ __forceinline__ void mmah(float c[4], const unsigned a[4], const unsigned b0,
                                     const unsigned b1) {
    asm volatile(
        "mma.sync.aligned.m16n8k16.row.col.f32.f16.f16.f32 "
        "{%0,%1,%2,%3}, {%4,%5,%6,%7}, {%8,%9}, {%0,%1,%2,%3};"
        : "+f"(c[0]), "+f"(c[1]), "+f"(c[2]), "+f"(c[3])
        : "r"(a[0]), "r"(a[1]), "r"(a[2]), "r"(a[3]), "r"(b0), "r"(b1));
}

#define LDSM4(r0, r1, r2, r3, addr) \
    asm volatile("ldmatrix.sync.aligned.m8n8.x4.shared.b16 {%0,%1,%2,%3}, [%4];" \
                 : "=r"(r0), "=r"(r1), "=r"(r2), "=r"(r3) : "r"(addr))

// ---------------- prep kernels ----------------------------------------------
__global__ void cvth_k(const float4* __restrict__ s, __half2* __restrict__ d, int n4) {
    int i = blockIdx.x * 256 + threadIdx.x;
    if (i < n4) {
        float4 v = s[i];
        d[2 * i + 0] = __floats2half2_rn(v.x, v.y);
        d[2 * i + 1] = __floats2half2_rn(v.z, v.w);
    }
}

// Wqkv: permute cols (h d qkv)->(qkv h d) AND transpose to [N=2304][K=768]
__global__ void permw_k(const float* __restrict__ W, const float* __restrict__ bias) {
    int gid = blockIdx.x * 256 + threadIdx.x;
    if (gid < NQKV * (EMB_ / 4)) {
        int j = gid / 192, k4 = gid - (gid / 192) * 192;
        int qkv = j / 768, hd = j - qkv * 768;
        int sc = hd * 3 + qkv;
        int k = k4 * 4;
        __half2 a = __floats2half2_rn(W[(size_t)(k + 0) * NQKV + sc],
                                      W[(size_t)(k + 1) * NQKV + sc]);
        __half2 b = __floats2half2_rn(W[(size_t)(k + 2) * NQKV + sc],
                                      W[(size_t)(k + 3) * NQKV + sc]);
        *(__half2*)(g_w1 + (size_t)j * EMB_ + k) = a;
        *(__half2*)(g_w1 + (size_t)j * EMB_ + k + 2) = b;
    }
    if (gid < NQKV) {
        int qkv = gid / 768, hd = gid - qkv * 768;
        g_b1[gid] = bias[hd * 3 + qkv];
    }
}

// Wproj: transpose to [N][K]
__global__ void transw2_k(const float* __restrict__ W) {
    int gid = blockIdx.x * 256 + threadIdx.x;
    if (gid < EMB_ * (EMB_ / 4)) {
        int n = gid / 192, k4 = gid - (gid / 192) * 192;
        int k = k4 * 4;
        __half2 a = __floats2half2_rn(W[(size_t)(k + 0) * EMB_ + n],
                                      W[(size_t)(k + 1) * EMB_ + n]);
        __half2 b = __floats2half2_rn(W[(size_t)(k + 2) * EMB_ + n],
                                      W[(size_t)(k + 3) * EMB_ + n]);
        *(__half2*)(g_w2 + (size_t)n * EMB_ + k) = a;
        *(__half2*)(g_w2 + (size_t)n * EMB_ + k + 2) = b;
    }
}

// ------- fp16 GEMM: C[M,N] = A[M,768] @ Wt[N,768]^T + b ---------------------
// 128x128 block, 4 warps @ 64x64 tiles, BK=64, 3-stage, LDSM + reg pipeline.
#define BM  128
#define BN  128
#define BKH 64
#define LD32 36           // words/row: 32 data + 4 pad (36 % 32 == 4)
#define STG 3
#define STW (BM * LD32 * 2)   // 9216 words / stage (36864 B)
#define NKT (EMB_ / BKH)      // 12

__device__ __forceinline__ void gemm_issue(
    uint32_t smb, const __half* __restrict__ A, const __half* __restrict__ Wt,
    int bm, int bn, int tid, int kt)
{
    const int k0 = kt * BKH;
    const uint32_t sb = smb + (uint32_t)((kt % STG) * STW) * 4u;
#pragma unroll
    for (int i = 0; i < 8; i++) {               // A: 128 rows x 8 x 16B
        int id = tid + 128 * i, r = id >> 3, c4 = id & 7;
        cpa16(sb + (uint32_t)(r * LD32 + c4 * 4) * 4u,
              A + (size_t)(bm + r) * EMB_ + k0 + c4 * 8);
    }
    const uint32_t sbB = sb + (uint32_t)(BM * LD32) * 4u;
#pragma unroll
    for (int i = 0; i < 8; i++) {               // B: 128 rows x 8 x 16B
        int id = tid + 128 * i, r = id >> 3, c4 = id & 7;
        cpa16(sbB + (uint32_t)(r * LD32 + c4 * 4) * 4u,
              Wt + (size_t)(bn + r) * EMB_ + k0 + c4 * 8);
    }
    CP_COMMIT();
}

__global__ __launch_bounds__(128, 2) void gemm_h(
    const __half* __restrict__ A, const __half* __restrict__ Wt,
    const float* __restrict__ bias, float* __restrict__ Cf, int qkv_mode)
{
    extern __shared__ unsigned smw[];
    const uint32_t smb = (uint32_t)__cvta_generic_to_shared(smw);

    const int bm = blockIdx.y * BM, bn = blockIdx.x * BN;
    const int tid = threadIdx.x;
    const int w = tid >> 5, lane = tid & 31, lq = lane >> 2, lr = lane & 3;
    const int wm = (w & 1) * 64, wn = (w >> 1) * 64;   // 2x2 warps, 64x64 tiles

    // per-lane LDSM offsets (words)
    const uint32_t offA = ((lane & 7) + ((lane >> 3) & 1) * 8) * LD32 + (lane >> 4) * 4;
    const uint32_t offB = ((lane & 7) + ((lane >> 4) & 1) * 8) * LD32 + ((lane >> 3) & 1) * 4;

    float acc[4][8][4];
#pragma unroll
    for (int i = 0; i < 4; i++)
#pragma unroll
        for (int j = 0; j < 8; j++)
#pragma unroll
            for (int q = 0; q < 4; q++) acc[i][j][q] = 0.f;

    gemm_issue(smb, A, Wt, bm, bn, tid, 0);
    gemm_issue(smb, A, Wt, bm, bn, tid, 1);

    for (int kt = 0; kt < NKT; ++kt) {
        if (kt + 1 < NKT) { CP_WAIT(1); } else { CP_WAIT(0); }
        __syncthreads();
        if (kt + 2 < NKT) gemm_issue(smb, A, Wt, bm, bn, tid, kt + 2);

        const uint32_t sA = smb + (uint32_t)((kt % STG) * STW) * 4u;
        const uint32_t sB = sA + (uint32_t)(BM * LD32) * 4u;

        unsigned af[2][4][4], bf[2][4][4];
        // preload kk=0 fragments
#pragma unroll
        for (int mi = 0; mi < 4; mi++)
            LDSM4(af[0][mi][0], af[0][mi][1], af[0][mi][2], af[0][mi][3],
                  sA + ((uint32_t)((wm + mi * 16) * LD32) + offA) * 4u);
#pragma unroll
        for (int p = 0; p < 4; p++)
            LDSM4(bf[0][p][0], bf[0][p][1], bf[0][p][2], bf[0][p][3],
                  sB + ((uint32_t)((wn + p * 16) * LD32) + offB) * 4u);

#pragma unroll
        for (int kk = 0; kk < 4; kk++) {        // 4 x k16 per BK=64
            const int cur = kk & 1, nxt = cur ^ 1;
            if (kk < 3) {                       // prefetch kk+1 before mmas
                const uint32_t kw = (kk + 1) * 8;
#pragma unroll
                for (int mi = 0; mi < 4; mi++)
                    LDSM4(af[nxt][mi][0], af[nxt][mi][1], af[nxt][mi][2], af[nxt][mi][3],
                          sA + ((uint32_t)((wm + mi * 16) * LD32) + kw + offA) * 4u);
#pragma unroll
                for (int p = 0; p < 4; p++)
                    LDSM4(bf[nxt][p][0], bf[nxt][p][1], bf[nxt][p][2], bf[nxt][p][3],
                          sB + ((uint32_t)((wn + p * 16) * LD32) + kw + offB) * 4u);
            }
#pragma unroll
            for (int p = 0; p < 4; p++)
#pragma unroll
                for (int mi = 0; mi < 4; mi++) {
                    mmah(acc[mi][2 * p], af[cur][mi], bf[cur][p][0], bf[cur][p][1]);
                    mmah(acc[mi][2 * p + 1], af[cur][mi], bf[cur][p][2], bf[cur][p][3]);
                }
        }
    }

    // epilogue
#pragma unroll
    for (int ni = 0; ni < 8; ni++) {
        int j = bn + wn + ni * 8 + 2 * lr;
        float b0 = bias[j], b1 = bias[j + 1];
        if (qkv_mode) {
            int plane = j / 768, pc = j - plane * 768;   // whole 128-tile in one plane
#pragma unroll
            for (int mi = 0; mi < 4; mi++) {
                int t = bm + wm + mi * 16 + lq;
#pragma unroll
                for (int hh = 0; hh < 2; hh++) {
                    int tt = t + 8 * hh;
                    float v0 = acc[mi][ni][2 * hh + 0] + b0;
                    float v1 = acc[mi][ni][2 * hh + 1] + b1;
                    if (plane == 0) {
                        *(unsigned*)(g_q + (size_t)tt * EMB_ + pc) =
                            packh(v0 * SCALE_Q, v1 * SCALE_Q);
                    } else if (plane == 1) {
                        *(unsigned*)(g_k + (size_t)tt * EMB_ + pc) = packh(v0, v1);
                    } else {
                        int b = tt >> 11, ntok = tt & 2047;
                        size_t base = ((size_t)b * EMB_ + pc) * SEQ + ntok;
                        g_vt[base] = __float2half_rn(v0);
                        g_vt[base + SEQ] = __float2half_rn(v1);
                    }
                }
            }
        } else {
#pragma unroll
            for (int mi = 0; mi < 4; mi++) {
                int t = bm + wm + mi * 16 + lq;
                *(float2*)(Cf + (size_t)t * EMB_ + j) =
                    make_float2(acc[mi][ni][0] + b0, acc[mi][ni][1] + b1);
                *(float2*)(Cf + (size_t)(t + 8) * EMB_ + j) =
                    make_float2(acc[mi][ni][2] + b0, acc[mi][ni][3] + b1);
            }
        }
    }
}

// -------- attention: fp16 FA2, warp-private 32 rows, hoisted Q frags --------
#define AQ   128
#define AKT  64                             // tokens per iter
#define LQ32 52                             // 48 data + 4 pad
#define LK32 52
#define LV32 36                             // 32 data + 4 pad
#define OFFK 6656                           // sQ = 128*52
#define OFFV (OFFK + 2 * AKT * LK32)        // 13312
#define ATTW (OFFV + 2 * HDIM * LV32)       // 20224 w (80896 B)
#define NIT (SEQ / AKT)                     // 32

__device__ __forceinline__ void attn_issue(
    uint32_t smb, const __half* __restrict__ Kg, const __half* __restrict__ Vtg,
    int tid, int it)
{
    const int base = it * AKT;
    const int buf = it & 1;
    const uint32_t kb = smb + (uint32_t)(OFFK + buf * (AKT * LK32)) * 4u;
#pragma unroll
    for (int i = 0; i < 6; i++) {           // K: 64 rows x 12 x 16B
        int id = tid + 128 * i, r = id / 12, c4 = id - r * 12;
        cpa16(kb + (uint32_t)(r * LK32 + c4 * 4) * 4u,
              Kg + (size_t)(base + r) * EMB_ + c4 * 8);
    }
    const uint32_t vb = smb + (uint32_t)(OFFV + buf * (HDIM * LV32)) * 4u;
#pragma unroll
    for (int i = 0; i < 6; i++) {           // Vt: 96 rows x 8 x 16B
        int id = tid + 128 * i, r = id >> 3, c4 = id & 7;
        cpa16(vb + (uint32_t)(r * LV32 + c4 * 4) * 4u,
              Vtg + (size_t)r * SEQ + base + c4 * 8);
    }
    CP_COMMIT();
}

__global__ __launch_bounds__(128, 2) void attn4() {
    extern __shared__ unsigned smw[];
    const uint32_t smb = (uint32_t)__cvta_generic_to_shared(smw);

    const int bh = blockIdx.y;
    const int qb = blockIdx.x * AQ;
    const int b = bh >> 3, h = bh & 7;
    const int tid = threadIdx.x, w = tid >> 5, lane = tid & 31;
    const int lq = lane >> 2, lr = lane & 3;
    const int wr = w * 32;                  // warp-private row base

    // per-lane LDSM offsets (words)
    const uint32_t offAq = ((lane & 7) + ((lane >> 3) & 1) * 8) * LQ32 + (lane >> 4) * 4;
    const uint32_t offBk = ((lane & 7) + ((lane >> 4) & 1) * 8) * LK32 + ((lane >> 3) & 1) * 4;
    const uint32_t offBv = ((lane & 7) + ((lane >> 4) & 1) * 8) * LV32 + ((lane >> 3) & 1) * 4;

    const __half* Qg = g_q + (size_t)(b * SEQ + qb) * EMB_ + h * HDIM;
    const __half* Kg = g_k + (size_t)(b * SEQ) * EMB_ + h * HDIM;
    const __half* Vtg = g_vt + ((size_t)b * EMB_ + h * HDIM) * SEQ;

    // prologue: Q tile (own commit group), then KV stage 0 (own group)
#pragma unroll
    for (int i = 0; i < 12; i++) {
        int id = tid + 128 * i, r = id / 12, c4 = id - r * 12;
        cpa16(smb + (uint32_t)(r * LQ32 + c4 * 4) * 4u,
              Qg + (size_t)r * EMB_ + c4 * 8);
    }
    CP_COMMIT();
    attn_issue(smb, Kg, Vtg, tid, 0);

    // hoist ALL Q fragments into registers (iteration-invariant)
    CP_WAIT(1);                             // Q group done (KV may be pending)
    __syncthreads();
    unsigned qf[6][2][4];
#pragma unroll
    for (int kk = 0; kk < 6; kk++)
#pragma unroll
        for (int mi = 0; mi < 2; mi++)
            LDSM4(qf[kk][mi][0], qf[kk][mi][1], qf[kk][mi][2], qf[kk][mi][3],
                  smb + ((uint32_t)((wr + mi * 16) * LQ32) + kk * 8 + offAq) * 4u);

    float o[2][12][4];
#pragma unroll
    for (int i = 0; i < 2; i++)
#pragma unroll
        for (int j = 0; j < 12; j++)
#pragma unroll
            for (int q = 0; q < 4; q++) o[i][j][q] = 0.f;
    float rs[2][2] = {{0.f, 0.f}, {0.f, 0.f}};

    for (int it = 0; it < NIT; ++it) {
        CP_WAIT(0);
        __syncthreads();
        if (it + 1 < NIT) attn_issue(smb, Kg, Vtg, tid, it + 1);

        const uint32_t cKb = smb + (uint32_t)(OFFK + (it & 1) * (AKT * LK32)) * 4u;
        const uint32_t cVb = smb + (uint32_t)(OFFV + (it & 1) * (HDIM * LV32)) * 4u;

        // S[32x64] per warp = Q @ K^T  (6 k16 steps over HDIM=96)
        float s[2][8][4];
#pragma unroll
        for (int i = 0; i < 2; i++)
#pragma unroll
            for (int j = 0; j < 8; j++)
#pragma unroll
                for (int q = 0; q < 4; q++) s[i][j][q] = 0.f;

#pragma unroll
        for (int kk = 0; kk < 6; kk++) {
            const uint32_t kw = kk * 8;
#pragma unroll
            for (int p = 0; p < 4; p++) {
                unsigned b0, b1, b2, b3;
                LDSM4(b0, b1, b2, b3,
                      cKb + ((uint32_t)(p * 16 * LK32) + kw + offBk) * 4u);
                mmah(s[0][2 * p], qf[kk][0], b0, b1);
                mmah(s[1][2 * p], qf[kk][1], b0, b1);
                mmah(s[0][2 * p + 1], qf[kk][0], b2, b3);
                mmah(s[1][2 * p + 1], qf[kk][1], b2, b3);
            }
        }

        // P = fp16(2^S), packed in-place as PV A-frag halves; f32 row sums
        unsigned ph[2][8][2];
#pragma unroll
        for (int mi = 0; mi < 2; mi++)
#pragma unroll
            for (int ni = 0; ni < 8; ni++) {
                unsigned u0 = packh(ex2f(s[mi][ni][0]), ex2f(s[mi][ni][1]));
                unsigned u1 = packh(ex2f(s[mi][ni][2]), ex2f(s[mi][ni][3]));
                ph[mi][ni][0] = u0;
                ph[mi][ni][1] = u1;
                float2 f0 = __half22float2(*(__half2*)&u0);
                float2 f1 = __half22float2(*(__half2*)&u1);
                rs[mi][0] += f0.x + f0.y;
                rs[mi][1] += f1.x + f1.y;
            }

        // O += P @ V : A-frags ARE the packed c-frags (no shuffles)
#pragma unroll
        for (int j = 0; j < 4; j++) {
            unsigned af[2][4];
#pragma unroll
            for (int mi = 0; mi < 2; mi++) {
                af[mi][0] = ph[mi][2 * j][0];
                af[mi][1] = ph[mi][2 * j][1];
                af[mi][2] = ph[mi][2 * j + 1][0];
                af[mi][3] = ph[mi][2 * j + 1][1];
            }
            const uint32_t kw = j * 8;
#pragma unroll
            for (int p = 0; p < 6; p++) {
                unsigned b0, b1, b2, b3;
                LDSM4(b0, b1, b2, b3,
                      cVb + ((uint32_t)(p * 16 * LV32) + kw + offBv) * 4u);
                mmah(o[0][2 * p], af[0], b0, b1);
                mmah(o[1][2 * p], af[1], b0, b1);
                mmah(o[0][2 * p + 1], af[0], b2, b3);
                mmah(o[1][2 * p + 1], af[1], b2, b3);
            }
        }
    }

    // quad-reduce row sums (cols partitioned over lr within each quad)
#pragma unroll
    for (int mi = 0; mi < 2; mi++)
#pragma unroll
        for (int half = 0; half < 2; half++) {
            float v = rs[mi][half];
            v += __shfl_xor_sync(0xffffffffu, v, 1);
            v += __shfl_xor_sync(0xffffffffu, v, 2);
            rs[mi][half] = v;
        }

    // normalize, write ctx fp16
#pragma unroll
    for (int mi = 0; mi < 2; mi++) {
        int r0 = wr + mi * 16 + lq;
        float inv0 = 1.f / rs[mi][0];
        float inv1 = 1.f / rs[mi][1];
        size_t t0 = (size_t)(b * SEQ + qb + r0) * EMB_ + h * HDIM;
        size_t t1 = (size_t)(b * SEQ + qb + r0 + 8) * EMB_ + h * HDIM;
#pragma unroll
        for (int ni = 0; ni < 12; ni++) {
            int col = ni * 8 + 2 * lr;
            *(unsigned*)(g_ctx + t0 + col) = packh(o[mi][ni][0] * inv0,
                                                   o[mi][ni][1] * inv0);
            *(unsigned*)(g_ctx + t1 + col) = packh(o[mi][ni][2] * inv1,
                                                   o[mi][ni][3] * inv1);
        }
    }
}

// ---------------- launch -----------------------------------------------------
extern "C" void kernel_launch(void* const* d_in, const int* in_sizes, int n_in,
                              void* d_out, int out_size) {
    const float* x     = (const float*)d_in[0];
    const float* Wqkv  = (const float*)d_in[1];
    const float* bqkv  = (const float*)d_in[2];
    const float* Wproj = (const float*)d_in[3];
    const float* bproj = (const float*)d_in[4];
    float* out = (float*)d_out;

    void *pxh, *pw1, *pb1, *pw2, *pctx;
    cudaGetSymbolAddress(&pxh, g_xh);
    cudaGetSymbolAddress(&pw1, g_w1);
    cudaGetSymbolAddress(&pb1, g_b1);
    cudaGetSymbolAddress(&pw2, g_w2);
    cudaGetSymbolAddress(&pctx, g_ctx);

    const int gemm_smem = STG * STW * 4;   // 110592 B -> 2 CTAs/SM
    const int attn_smem = ATTW * 4;        // 80896 B  -> 2 CTAs/SM
    cudaFuncSetAttribute(gemm_h, cudaFuncAttributeMaxDynamicSharedMemorySize, gemm_smem);
    cudaFuncSetAttribute(attn4, cudaFuncAttributeMaxDynamicSharedMemorySize, attn_smem);

    // 0) prep: fp16 conversions (+ weight permute/transpose)
    cvth_k<<<(TOK * EMB_ / 4 + 255) / 256, 256>>>(
        (const float4*)x, (__half2*)pxh, TOK * EMB_ / 4);
    permw_k<<<(NQKV * (EMB_ / 4) + 255) / 256, 256>>>(Wqkv, bqkv);
    transw2_k<<<(EMB_ * (EMB_ / 4) + 255) / 256, 256>>>(Wproj);

    // 1) qkv = x @ Wqkv'^T + bqkv' -> q (scaled), k, v-transposed planes
    gemm_h<<<dim3(NQKV / BN, TOK / BM), 128, gemm_smem>>>(
        (const __half*)pxh, (const __half*)pw1, (const float*)pb1, nullptr, 1);

    // 2) attention -> ctx (fp16)
    attn4<<<dim3(SEQ / AQ, 32), 128, attn_smem>>>();

    // 3) out = ctx @ Wproj^T + bproj (fp32 out)
    gemm_h<<<dim3(EMB_ / BN, TOK / BM), 128, gemm_smem>>>(
        (const __half*)pctx, (const __half*)pw2, bproj, out, 0);
}

// round 16
// speedup vs baseline: 1.0468x; 1.0468x over previous
#include <cuda_runtime.h>
#include <cuda_fp16.h>
#include <cstdint>

// Problem constants
#define TOK    8192
#define EMB_   768
#define NQKV   2304
#define HDIM   96
#define SEQ    2048

// log2(e)/sqrt(768): folded into q so softmax is a bare ex2.approx
#define SCALE_Q 0.05205875899635608f

// ---------------- scratch (static device globals) ---------------------------
__device__ __half g_xh[TOK * EMB_];     // fp16 x
__device__ __half g_w1[NQKV * EMB_];    // permuted+transposed Wqkv  [N][K]
__device__ float  g_b1[NQKV];           // permuted bqkv (fp32)
__device__ __half g_w2[EMB_ * EMB_];    // transposed Wproj [N][K]
__device__ __half g_q[TOK * EMB_];      // [b][tok][h*96+d], pre-scaled
__device__ __half g_k[TOK * EMB_];      // [b][tok][h*96+d]
__device__ __half g_vt[TOK * EMB_];     // transposed: [b][h*96+d][tok]
__device__ __half g_ctx[TOK * EMB_];    // attention out, fp16

// ---------------- helpers ---------------------------------------------------
__device__ __forceinline__ float ex2f(float x) {
    float y;
    asm("ex2.approx.f32 %0, %1;" : "=f"(y) : "f"(x));
    return y;
}
__device__ __forceinline__ unsigned packh(float lo, float hi) {
    unsigned u;
    asm("cvt.rn.f16x2.f32 %0, %1, %2;" : "=r"(u) : "f"(hi), "f"(lo));
    return u;
}
__device__ __forceinline__ void cpa16(uint32_t dst, const void* src) {
    asm volatile("cp.async.cg.shared.global [%0], [%1], 16;" :: "r"(dst), "l"(src));
}
#define CP_COMMIT() asm volatile("cp.async.commit_group;")
#define CP_WAIT(n)  asm volatile("cp.async.wait_group %0;" :: "n"(n))

// D += A(16x16,row) * B(16x8,col), fp16 in / f32 acc
__device__ __forceinline__ void mmah(float c[4], const unsigned a[4], const unsigned b0,
                                     const unsigned b1) {
    asm volatile(
        "mma.sync.aligned.m16n8k16.row.col.f32.f16.f16.f32 "
        "{%0,%1,%2,%3}, {%4,%5,%6,%7}, {%8,%9}, {%0,%1,%2,%3};"
        : "+f"(c[0]), "+f"(c[1]), "+f"(c[2]), "+f"(c[3])
        : "r"(a[0]), "r"(a[1]), "r"(a[2]), "r"(a[3]), "r"(b0), "r"(b1));
}

#define LDSM4(r0, r1, r2, r3, addr) \
    asm volatile("ldmatrix.sync.aligned.m8n8.x4.shared.b16 {%0,%1,%2,%3}, [%4];" \
                 : "=r"(r0), "=r"(r1), "=r"(r2), "=r"(r3) : "r"(addr))

// ---------------- prep kernels ----------------------------------------------
__global__ void cvth_k(const float4* __restrict__ s, __half2* __restrict__ d, int n4) {
    int i = blockIdx.x * 256 + threadIdx.x;
    if (i < n4) {
        float4 v = s[i];
        d[2 * i + 0] = __floats2half2_rn(v.x, v.y);
        d[2 * i + 1] = __floats2half2_rn(v.z, v.w);
    }
}

__global__ void permb_k(const float* __restrict__ bias) {
    int gid = blockIdx.x * 256 + threadIdx.x;
    if (gid < NQKV) {
        int qkv = gid / 768, hd = gid - qkv * 768;
        g_b1[gid] = bias[hd * 3 + qkv];
    }
}

// Wqkv permute+transpose via smem tiles: g_w1[j][k] = fp16(W[k][sc(j)])
__global__ void permw_t(const float* __restrict__ W) {
    __shared__ __half sm[32][33];
    const int tx = threadIdx.x, ty = threadIdx.y;       // 32 x 8
    const int j0 = blockIdx.x * 32, k0 = blockIdx.y * 32;
    int j = j0 + tx;
    int qkv = j / 768, hd = j - qkv * 768;
    int sc = hd * 3 + qkv;
#pragma unroll
    for (int r = 0; r < 4; r++) {
        int k = k0 + ty + 8 * r;
        sm[ty + 8 * r][tx] = __float2half_rn(W[(size_t)k * NQKV + sc]);
    }
    __syncthreads();
#pragma unroll
    for (int r = 0; r < 4; r++) {
        int j2 = j0 + ty + 8 * r;
        g_w1[(size_t)j2 * EMB_ + k0 + tx] = sm[tx][ty + 8 * r];
    }
}

// Wproj transpose via smem tiles: g_w2[n][k] = fp16(W[k][n])
__global__ void transw2_t(const float* __restrict__ W) {
    __shared__ __half sm[32][33];
    const int tx = threadIdx.x, ty = threadIdx.y;       // 32 x 8
    const int n0 = blockIdx.x * 32, k0 = blockIdx.y * 32;
#pragma unroll
    for (int r = 0; r < 4; r++) {
        int k = k0 + ty + 8 * r;
        sm[ty + 8 * r][tx] = __float2half_rn(W[(size_t)k * EMB_ + n0 + tx]);
    }
    __syncthreads();
#pragma unroll
    for (int r = 0; r < 4; r++) {
        int n2 = n0 + ty + 8 * r;
        g_w2[(size_t)n2 * EMB_ + k0 + tx] = sm[tx][ty + 8 * r];
    }
}

// ------- fp16 GEMM: C[M,N] = A[M,768] @ Wt[N,768]^T + b ---------------------
// 128x128 block, 256 thr / 8 warps @ 32x64 tiles, BK=64, 3-stage, LDSM.
#define BM  128
#define BN  128
#define BKH 64
#define LD32 36           // words/row: 32 data + 4 pad (36 % 32 == 4)
#define STG 3
#define STW (BM * LD32 * 2)   // 9216 words / stage (36864 B)
#define NKT (EMB_ / BKH)      // 12

__device__ __forceinline__ void gemm_issue(
    uint32_t smb, const __half* __restrict__ A, const __half* __restrict__ Wt,
    int bm, int bn, int tid, int kt)
{
    const int k0 = kt * BKH;
    const uint32_t sb = smb + (uint32_t)((kt % STG) * STW) * 4u;
#pragma unroll
    for (int i = 0; i < 4; i++) {               // A: 128 rows x 8 x 16B
        int id = tid + 256 * i, r = id >> 3, c4 = id & 7;
        cpa16(sb + (uint32_t)(r * LD32 + c4 * 4) * 4u,
              A + (size_t)(bm + r) * EMB_ + k0 + c4 * 8);
    }
    const uint32_t sbB = sb + (uint32_t)(BM * LD32) * 4u;
#pragma unroll
    for (int i = 0; i < 4; i++) {               // B: 128 rows x 8 x 16B
        int id = tid + 256 * i, r = id >> 3, c4 = id & 7;
        cpa16(sbB + (uint32_t)(r * LD32 + c4 * 4) * 4u,
              Wt + (size_t)(bn + r) * EMB_ + k0 + c4 * 8);
    }
    CP_COMMIT();
}

__global__ __launch_bounds__(256, 2) void gemm_h(
    const __half* __restrict__ A, const __half* __restrict__ Wt,
    const float* __restrict__ bias, float* __restrict__ Cf, int qkv_mode)
{
    extern __shared__ unsigned smw[];
    const uint32_t smb = (uint32_t)__cvta_generic_to_shared(smw);

    const int bm = blockIdx.y * BM, bn = blockIdx.x * BN;
    const int tid = threadIdx.x;
    const int w = tid >> 5, lane = tid & 31, lq = lane >> 2, lr = lane & 3;
    const int wm = (w & 3) * 32, wn = (w >> 2) * 64;   // 4 m-warps x 2 n-warps

    // per-lane LDSM offsets (words)
    const uint32_t offA = ((lane & 7) + ((lane >> 3) & 1) * 8) * LD32 + (lane >> 4) * 4;
    const uint32_t offB = ((lane & 7) + ((lane >> 4) & 1) * 8) * LD32 + ((lane >> 3) & 1) * 4;

    float acc[2][8][4];
#pragma unroll
    for (int i = 0; i < 2; i++)
#pragma unroll
        for (int j = 0; j < 8; j++)
#pragma unroll
            for (int q = 0; q < 4; q++) acc[i][j][q] = 0.f;

    gemm_issue(smb, A, Wt, bm, bn, tid, 0);
    gemm_issue(smb, A, Wt, bm, bn, tid, 1);

    for (int kt = 0; kt < NKT; ++kt) {
        if (kt + 1 < NKT) { CP_WAIT(1); } else { CP_WAIT(0); }
        __syncthreads();
        if (kt + 2 < NKT) gemm_issue(smb, A, Wt, bm, bn, tid, kt + 2);

        const uint32_t sA = smb + (uint32_t)((kt % STG) * STW) * 4u;
        const uint32_t sB = sA + (uint32_t)(BM * LD32) * 4u;

#pragma unroll
        for (int kk = 0; kk < 4; kk++) {        // 4 x k16 per BK=64
            const uint32_t kw = kk * 8;
            unsigned af[2][4];
#pragma unroll
            for (int mi = 0; mi < 2; mi++)
                LDSM4(af[mi][0], af[mi][1], af[mi][2], af[mi][3],
                      sA + ((uint32_t)((wm + mi * 16) * LD32) + kw + offA) * 4u);
#pragma unroll
            for (int p = 0; p < 4; p++) {
                unsigned b0, b1, b2, b3;
                LDSM4(b0, b1, b2, b3,
                      sB + ((uint32_t)((wn + p * 16) * LD32) + kw + offB) * 4u);
                mmah(acc[0][2 * p], af[0], b0, b1);
                mmah(acc[1][2 * p], af[1], b0, b1);
                mmah(acc[0][2 * p + 1], af[0], b2, b3);
                mmah(acc[1][2 * p + 1], af[1], b2, b3);
            }
        }
    }

    // epilogue
#pragma unroll
    for (int ni = 0; ni < 8; ni++) {
        int j = bn + wn + ni * 8 + 2 * lr;
        float b0 = bias[j], b1 = bias[j + 1];
        if (qkv_mode) {
            int plane = j / 768, pc = j - plane * 768;
#pragma unroll
            for (int mi = 0; mi < 2; mi++) {
                int t = bm + wm + mi * 16 + lq;
#pragma unroll
                for (int hh = 0; hh < 2; hh++) {
                    int tt = t + 8 * hh;
                    float v0 = acc[mi][ni][2 * hh + 0] + b0;
                    float v1 = acc[mi][ni][2 * hh + 1] + b1;
                    if (plane == 0) {
                        *(unsigned*)(g_q + (size_t)tt * EMB_ + pc) =
                            packh(v0 * SCALE_Q, v1 * SCALE_Q);
                    } else if (plane == 1) {
                        *(unsigned*)(g_k + (size_t)tt * EMB_ + pc) = packh(v0, v1);
                    } else {
                        int b = tt >> 11, ntok = tt & 2047;
                        size_t base = ((size_t)b * EMB_ + pc) * SEQ + ntok;
                        g_vt[base] = __float2half_rn(v0);
                        g_vt[base + SEQ] = __float2half_rn(v1);
                    }
                }
            }
        } else {
#pragma unroll
            for (int mi = 0; mi < 2; mi++) {
                int t = bm + wm + mi * 16 + lq;
                *(float2*)(Cf + (size_t)t * EMB_ + j) =
                    make_float2(acc[mi][ni][0] + b0, acc[mi][ni][1] + b1);
                *(float2*)(Cf + (size_t)(t + 8) * EMB_ + j) =
                    make_float2(acc[mi][ni][2] + b0, acc[mi][ni][3] + b1);
            }
        }
    }
}

// -------- attention: fp16 FA2, warp-private 32 rows, LDSM frags -------------
// (reverted to the 309.8us shape; proper commit-group discipline)
#define AQ   128
#define AKT  64                             // tokens per iter
#define LQ32 52                             // 48 data + 4 pad
#define LK32 52
#define LV32 36                             // 32 data + 4 pad
#define OFFK 6656                           // sQ = 128*52
#define OFFV (OFFK + 2 * AKT * LK32)        // 13312
#define ATTW (OFFV + 2 * HDIM * LV32)       // 20224 w (80896 B)
#define NIT (SEQ / AKT)                     // 32

__device__ __forceinline__ void attn_issue(
    uint32_t smb, const __half* __restrict__ Kg, const __half* __restrict__ Vtg,
    int tid, int it)
{
    const int base = it * AKT;
    const int buf = it & 1;
    const uint32_t kb = smb + (uint32_t)(OFFK + buf * (AKT * LK32)) * 4u;
#pragma unroll
    for (int i = 0; i < 6; i++) {           // K: 64 rows x 12 x 16B
        int id = tid + 128 * i, r = id / 12, c4 = id - r * 12;
        cpa16(kb + (uint32_t)(r * LK32 + c4 * 4) * 4u,
              Kg + (size_t)(base + r) * EMB_ + c4 * 8);
    }
    const uint32_t vb = smb + (uint32_t)(OFFV + buf * (HDIM * LV32)) * 4u;
#pragma unroll
    for (int i = 0; i < 6; i++) {           // Vt: 96 rows x 8 x 16B
        int id = tid + 128 * i, r = id >> 3, c4 = id & 7;
        cpa16(vb + (uint32_t)(r * LV32 + c4 * 4) * 4u,
              Vtg + (size_t)r * SEQ + base + c4 * 8);
    }
    CP_COMMIT();
}

__global__ __launch_bounds__(128, 2) void attn4() {
    extern __shared__ unsigned smw[];
    const uint32_t smb = (uint32_t)__cvta_generic_to_shared(smw);

    const int bh = blockIdx.y;
    const int qb = blockIdx.x * AQ;
    const int b = bh >> 3, h = bh & 7;
    const int tid = threadIdx.x, w = tid >> 5, lane = tid & 31;
    const int lq = lane >> 2, lr = lane & 3;
    const int wr = w * 32;                  // warp-private row base

    // per-lane LDSM offsets (words)
    const uint32_t offAq = ((lane & 7) + ((lane >> 3) & 1) * 8) * LQ32 + (lane >> 4) * 4;
    const uint32_t offBk = ((lane & 7) + ((lane >> 4) & 1) * 8) * LK32 + ((lane >> 3) & 1) * 4;
    const uint32_t offBv = ((lane & 7) + ((lane >> 4) & 1) * 8) * LV32 + ((lane >> 3) & 1) * 4;

    const __half* Qg = g_q + (size_t)(b * SEQ + qb) * EMB_ + h * HDIM;
    const __half* Kg = g_k + (size_t)(b * SEQ) * EMB_ + h * HDIM;
    const __half* Vtg = g_vt + ((size_t)b * EMB_ + h * HDIM) * SEQ;

    // prologue: Q tile + KV stage 0 (single commit group via attn_issue)
#pragma unroll
    for (int i = 0; i < 12; i++) {
        int id = tid + 128 * i, r = id / 12, c4 = id - r * 12;
        cpa16(smb + (uint32_t)(r * LQ32 + c4 * 4) * 4u,
              Qg + (size_t)r * EMB_ + c4 * 8);
    }
    attn_issue(smb, Kg, Vtg, tid, 0);

    float o[2][12][4];
#pragma unroll
    for (int i = 0; i < 2; i++)
#pragma unroll
        for (int j = 0; j < 12; j++)
#pragma unroll
            for (int q = 0; q < 4; q++) o[i][j][q] = 0.f;
    float rs[2][2] = {{0.f, 0.f}, {0.f, 0.f}};

    for (int it = 0; it < NIT; ++it) {
        CP_WAIT(0);
        __syncthreads();
        if (it + 1 < NIT) attn_issue(smb, Kg, Vtg, tid, it + 1);

        const uint32_t cKb = smb + (uint32_t)(OFFK + (it & 1) * (AKT * LK32)) * 4u;
        const uint32_t cVb = smb + (uint32_t)(OFFV + (it & 1) * (HDIM * LV32)) * 4u;

        // S[32x64] per warp = Q @ K^T  (6 k16 steps over HDIM=96)
        float s[2][8][4];
#pragma unroll
        for (int i = 0; i < 2; i++)
#pragma unroll
            for (int j = 0; j < 8; j++)
#pragma unroll
                for (int q = 0; q < 4; q++) s[i][j][q] = 0.f;

#pragma unroll
        for (int kk = 0; kk < 6; kk++) {
            const uint32_t kw = kk * 8;
            unsigned af[2][4];
#pragma unroll
            for (int mi = 0; mi < 2; mi++)
                LDSM4(af[mi][0], af[mi][1], af[mi][2], af[mi][3],
                      smb + ((uint32_t)((wr + mi * 16) * LQ32) + kw + offAq) * 4u);
#pragma unroll
            for (int p = 0; p < 4; p++) {
                unsigned b0, b1, b2, b3;
                LDSM4(b0, b1, b2, b3,
                      cKb + ((uint32_t)(p * 16 * LK32) + kw + offBk) * 4u);
                mmah(s[0][2 * p], af[0], b0, b1);
                mmah(s[1][2 * p], af[1], b0, b1);
                mmah(s[0][2 * p + 1], af[0], b2, b3);
                mmah(s[1][2 * p + 1], af[1], b2, b3);
            }
        }

        // P = fp16(2^S), packed in-place as PV A-frag halves; f32 row sums
        unsigned ph[2][8][2];
#pragma unroll
        for (int mi = 0; mi < 2; mi++)
#pragma unroll
            for (int ni = 0; ni < 8; ni++) {
                unsigned u0 = packh(ex2f(s[mi][ni][0]), ex2f(s[mi][ni][1]));
                unsigned u1 = packh(ex2f(s[mi][ni][2]), ex2f(s[mi][ni][3]));
                ph[mi][ni][0] = u0;
                ph[mi][ni][1] = u1;
                float2 f0 = __half22float2(*(__half2*)&u0);
                float2 f1 = __half22float2(*(__half2*)&u1);
                rs[mi][0] += f0.x + f0.y;
                rs[mi][1] += f1.x + f1.y;
            }

        // O += P @ V : A-frags ARE the packed c-frags (no shuffles)
#pragma unroll
        for (int j = 0; j < 4; j++) {
            unsigned af[2][4];
#pragma unroll
            for (int mi = 0; mi < 2; mi++) {
                af[mi][0] = ph[mi][2 * j][0];
                af[mi][1] = ph[mi][2 * j][1];
                af[mi][2] = ph[mi][2 * j + 1][0];
                af[mi][3] = ph[mi][2 * j + 1][1];
            }
            const uint32_t kw = j * 8;
#pragma unroll
            for (int p = 0; p < 6; p++) {
                unsigned b0, b1, b2, b3;
                LDSM4(b0, b1, b2, b3,
                      cVb + ((uint32_t)(p * 16 * LV32) + kw + offBv) * 4u);
                mmah(o[0][2 * p], af[0], b0, b1);
                mmah(o[1][2 * p], af[1], b0, b1);
                mmah(o[0][2 * p + 1], af[0], b2, b3);
                mmah(o[1][2 * p + 1], af[1], b2, b3);
            }
        }
    }

    // quad-reduce row sums (cols partitioned over lr within each quad)
#pragma unroll
    for (int mi = 0; mi < 2; mi++)
#pragma unroll
        for (int half = 0; half < 2; half++) {
            float v = rs[mi][half];
            v += __shfl_xor_sync(0xffffffffu, v, 1);
            v += __shfl_xor_sync(0xffffffffu, v, 2);
            rs[mi][half] = v;
        }

    // normalize, write ctx fp16
#pragma unroll
    for (int mi = 0; mi < 2; mi++) {
        int r0 = wr + mi * 16 + lq;
        float inv0 = 1.f / rs[mi][0];
        float inv1 = 1.f / rs[mi][1];
        size_t t0 = (size_t)(b * SEQ + qb + r0) * EMB_ + h * HDIM;
        size_t t1 = (size_t)(b * SEQ + qb + r0 + 8) * EMB_ + h * HDIM;
#pragma unroll
        for (int ni = 0; ni < 12; ni++) {
            int col = ni * 8 + 2 * lr;
            *(unsigned*)(g_ctx + t0 + col) = packh(o[mi][ni][0] * inv0,
                                                   o[mi][ni][1] * inv0);
            *(unsigned*)(g_ctx + t1 + col) = packh(o[mi][ni][2] * inv1,
                                                   o[mi][ni][3] * inv1);
        }
    }
}

// ---------------- launch -----------------------------------------------------
extern "C" void kernel_launch(void* const* d_in, const int* in_sizes, int n_in,
                              void* d_out, int out_size) {
    const float* x     = (const float*)d_in[0];
    const float* Wqkv  = (const float*)d_in[1];
    const float* bqkv  = (const float*)d_in[2];
    const float* Wproj = (const float*)d_in[3];
    const float* bproj = (const float*)d_in[4];
    float* out = (float*)d_out;

    void *pxh, *pw1, *pb1, *pw2, *pctx;
    cudaGetSymbolAddress(&pxh, g_xh);
    cudaGetSymbolAddress(&pw1, g_w1);
    cudaGetSymbolAddress(&pb1, g_b1);
    cudaGetSymbolAddress(&pw2, g_w2);
    cudaGetSymbolAddress(&pctx, g_ctx);

    const int gemm_smem = STG * STW * 4;   // 110592 B -> 2 CTAs/SM (16 warps)
    const int attn_smem = ATTW * 4;        // 80896 B  -> 2 CTAs/SM
    cudaFuncSetAttribute(gemm_h, cudaFuncAttributeMaxDynamicSharedMemorySize, gemm_smem);
    cudaFuncSetAttribute(attn4, cudaFuncAttributeMaxDynamicSharedMemorySize, attn_smem);

    // 0) prep: fp16 convert x; smem-transpose weight permutes; bias permute
    cvth_k<<<(TOK * EMB_ / 4 + 255) / 256, 256>>>(
        (const float4*)x, (__half2*)pxh, TOK * EMB_ / 4);
    permw_t<<<dim3(NQKV / 32, EMB_ / 32), dim3(32, 8)>>>(Wqkv);
    transw2_t<<<dim3(EMB_ / 32, EMB_ / 32), dim3(32, 8)>>>(Wproj);
    permb_k<<<(NQKV + 255) / 256, 256>>>(bqkv);

    // 1) qkv = x @ Wqkv'^T + bqkv' -> q (scaled), k, v-transposed planes
    gemm_h<<<dim3(NQKV / BN, TOK / BM), 256, gemm_smem>>>(
        (const __half*)pxh, (const __half*)pw1, (const float*)pb1, nullptr, 1);

    // 2) attention -> ctx (fp16)
    attn4<<<dim3(SEQ / AQ, 32), 128, attn_smem>>>();

    // 3) out = ctx @ Wproj^T + bproj (fp32 out)
    gemm_h<<<dim3(EMB_ / BN, TOK / BM), 256, gemm_smem>>>(
        (const __half*)pctx, (const __half*)pw2, bproj, out, 0);
}

// round 17
// speedup vs baseline: 1.0558x; 1.0086x over previous
#include <cuda_runtime.h>
#include <cuda_fp16.h>
#include <cstdint>

// Problem constants
#define TOK    8192
#define EMB_   768
#define NQKV   2304
#define HDIM   96
#define SEQ    2048

// log2(e)/sqrt(768): folded into q so softmax is a bare ex2.approx
#define SCALE_Q 0.05205875899635608f

// ---------------- scratch (static device globals) ---------------------------
__device__ __half g_xh[TOK * EMB_];     // fp16 x
__device__ __half g_w1[NQKV * EMB_];    // permuted+transposed Wqkv  [N][K]
__device__ float  g_b1[NQKV];           // permuted bqkv (fp32)
__device__ __half g_w2[EMB_ * EMB_];    // transposed Wproj [N][K]
__device__ __half g_q[TOK * EMB_];      // [b][tok][h*96+d], pre-scaled
__device__ __half g_k[TOK * EMB_];      // [b][tok][h*96+d]
__device__ __half g_v[TOK * EMB_];      // [b][tok][h*96+d] (row-major, like k)
__device__ __half g_ctx[TOK * EMB_];    // attention out, fp16

// ---------------- helpers ---------------------------------------------------
__device__ __forceinline__ float ex2f(float x) {
    float y;
    asm("ex2.approx.f32 %0, %1;" : "=f"(y) : "f"(x));
    return y;
}
__device__ __forceinline__ unsigned packh(float lo, float hi) {
    unsigned u;
    asm("cvt.rn.f16x2.f32 %0, %1, %2;" : "=r"(u) : "f"(hi), "f"(lo));
    return u;
}
__device__ __forceinline__ void cpa16(uint32_t dst, const void* src) {
    asm volatile("cp.async.cg.shared.global [%0], [%1], 16;" :: "r"(dst), "l"(src));
}
#define CP_COMMIT() asm volatile("cp.async.commit_group;")
#define CP_WAIT(n)  asm volatile("cp.async.wait_group %0;" :: "n"(n))

// D += A(16x16,row) * B(16x8,col), fp16 in / f32 acc
__device__ __forceinline__ void mmah(float c[4], const unsigned a[4], const unsigned b0,
                                     const unsigned b1) {
    asm volatile(
        "mma.sync.aligned.m16n8k16.row.col.f32.f16.f16.f32 "
        "{%0,%1,%2,%3}, {%4,%5,%6,%7}, {%8,%9}, {%0,%1,%2,%3};"
        : "+f"(c[0]), "+f"(c[1]), "+f"(c[2]), "+f"(c[3])
        : "r"(a[0]), "r"(a[1]), "r"(a[2]), "r"(a[3]), "r"(b0), "r"(b1));
}

#define LDSM4(r0, r1, r2, r3, addr) \
    asm volatile("ldmatrix.sync.aligned.m8n8.x4.shared.b16 {%0,%1,%2,%3}, [%4];" \
                 : "=r"(r0), "=r"(r1), "=r"(r2), "=r"(r3) : "r"(addr))
#define LDSM4T(r0, r1, r2, r3, addr) \
    asm volatile("ldmatrix.sync.aligned.m8n8.x4.trans.shared.b16 {%0,%1,%2,%3}, [%4];" \
                 : "=r"(r0), "=r"(r1), "=r"(r2), "=r"(r3) : "r"(addr))

// ---------------- prep kernels ----------------------------------------------
__global__ void cvth_k(const float4* __restrict__ s, __half2* __restrict__ d, int n4) {
    int i = blockIdx.x * 256 + threadIdx.x;
    if (i < n4) {
        float4 v = s[i];
        d[2 * i + 0] = __floats2half2_rn(v.x, v.y);
        d[2 * i + 1] = __floats2half2_rn(v.z, v.w);
    }
}

// Wqkv permute+transpose via smem tiles: g_w1[j][k] = fp16(W[k][sc(j)]); +bias
__global__ void permw_t(const float* __restrict__ W, const float* __restrict__ bias) {
    __shared__ __half sm[32][33];
    const int tx = threadIdx.x, ty = threadIdx.y;       // 32 x 8
    const int j0 = blockIdx.x * 32, k0 = blockIdx.y * 32;
    int j = j0 + tx;
    int qkv = j / 768, hd = j - qkv * 768;
    int sc = hd * 3 + qkv;
    if (blockIdx.y == 0 && ty == 0) g_b1[j] = bias[sc];
#pragma unroll
    for (int r = 0; r < 4; r++) {
        int k = k0 + ty + 8 * r;
        sm[ty + 8 * r][tx] = __float2half_rn(W[(size_t)k * NQKV + sc]);
    }
    __syncthreads();
#pragma unroll
    for (int r = 0; r < 4; r++) {
        int j2 = j0 + ty + 8 * r;
        g_w1[(size_t)j2 * EMB_ + k0 + tx] = sm[tx][ty + 8 * r];
    }
}

// Wproj transpose via smem tiles: g_w2[n][k] = fp16(W[k][n])
__global__ void transw2_t(const float* __restrict__ W) {
    __shared__ __half sm[32][33];
    const int tx = threadIdx.x, ty = threadIdx.y;       // 32 x 8
    const int n0 = blockIdx.x * 32, k0 = blockIdx.y * 32;
#pragma unroll
    for (int r = 0; r < 4; r++) {
        int k = k0 + ty + 8 * r;
        sm[ty + 8 * r][tx] = __float2half_rn(W[(size_t)k * EMB_ + n0 + tx]);
    }
    __syncthreads();
#pragma unroll
    for (int r = 0; r < 4; r++) {
        int n2 = n0 + ty + 8 * r;
        g_w2[(size_t)n2 * EMB_ + k0 + tx] = sm[tx][ty + 8 * r];
    }
}

// ------- fp16 GEMM: C[M,N] = A[M,768] @ Wt[N,768]^T + b ---------------------
// 128x128 block, 256 thr / 8 warps @ 32x64 tiles, BK=64, 3-stage, LDSM.
#define BM  128
#define BN  128
#define BKH 64
#define LD32 36           // words/row: 32 data + 4 pad (36 % 32 == 4)
#define STG 3
#define STW (BM * LD32 * 2)   // 9216 words / stage (36864 B)
#define NKT (EMB_ / BKH)      // 12

__device__ __forceinline__ void gemm_issue(
    uint32_t smb, const __half* __restrict__ A, const __half* __restrict__ Wt,
    int bm, int bn, int tid, int kt)
{
    const int k0 = kt * BKH;
    const uint32_t sb = smb + (uint32_t)((kt % STG) * STW) * 4u;
#pragma unroll
    for (int i = 0; i < 4; i++) {               // A: 128 rows x 8 x 16B
        int id = tid + 256 * i, r = id >> 3, c4 = id & 7;
        cpa16(sb + (uint32_t)(r * LD32 + c4 * 4) * 4u,
              A + (size_t)(bm + r) * EMB_ + k0 + c4 * 8);
    }
    const uint32_t sbB = sb + (uint32_t)(BM * LD32) * 4u;
#pragma unroll
    for (int i = 0; i < 4; i++) {               // B: 128 rows x 8 x 16B
        int id = tid + 256 * i, r = id >> 3, c4 = id & 7;
        cpa16(sbB + (uint32_t)(r * LD32 + c4 * 4) * 4u,
              Wt + (size_t)(bn + r) * EMB_ + k0 + c4 * 8);
    }
    CP_COMMIT();
}

__global__ __launch_bounds__(256, 2) void gemm_h(
    const __half* __restrict__ A, const __half* __restrict__ Wt,
    const float* __restrict__ bias, float* __restrict__ Cf, int qkv_mode)
{
    extern __shared__ unsigned smw[];
    const uint32_t smb = (uint32_t)__cvta_generic_to_shared(smw);

    const int bm = blockIdx.y * BM, bn = blockIdx.x * BN;
    const int tid = threadIdx.x;
    const int w = tid >> 5, lane = tid & 31, lq = lane >> 2, lr = lane & 3;
    const int wm = (w & 3) * 32, wn = (w >> 2) * 64;   // 4 m-warps x 2 n-warps

    // per-lane LDSM offsets (words)
    const uint32_t offA = ((lane & 7) + ((lane >> 3) & 1) * 8) * LD32 + (lane >> 4) * 4;
    const uint32_t offB = ((lane & 7) + ((lane >> 4) & 1) * 8) * LD32 + ((lane >> 3) & 1) * 4;

    float acc[2][8][4];
#pragma unroll
    for (int i = 0; i < 2; i++)
#pragma unroll
        for (int j = 0; j < 8; j++)
#pragma unroll
            for (int q = 0; q < 4; q++) acc[i][j][q] = 0.f;

    gemm_issue(smb, A, Wt, bm, bn, tid, 0);
    gemm_issue(smb, A, Wt, bm, bn, tid, 1);

    for (int kt = 0; kt < NKT; ++kt) {
        if (kt + 1 < NKT) { CP_WAIT(1); } else { CP_WAIT(0); }
        __syncthreads();
        if (kt + 2 < NKT) gemm_issue(smb, A, Wt, bm, bn, tid, kt + 2);

        const uint32_t sA = smb + (uint32_t)((kt % STG) * STW) * 4u;
        const uint32_t sB = sA + (uint32_t)(BM * LD32) * 4u;

#pragma unroll
        for (int kk = 0; kk < 4; kk++) {        // 4 x k16 per BK=64
            const uint32_t kw = kk * 8;
            unsigned af[2][4];
#pragma unroll
            for (int mi = 0; mi < 2; mi++)
                LDSM4(af[mi][0], af[mi][1], af[mi][2], af[mi][3],
                      sA + ((uint32_t)((wm + mi * 16) * LD32) + kw + offA) * 4u);
#pragma unroll
            for (int p = 0; p < 4; p++) {
                unsigned b0, b1, b2, b3;
                LDSM4(b0, b1, b2, b3,
                      sB + ((uint32_t)((wn + p * 16) * LD32) + kw + offB) * 4u);
                mmah(acc[0][2 * p], af[0], b0, b1);
                mmah(acc[1][2 * p], af[1], b0, b1);
                mmah(acc[0][2 * p + 1], af[0], b2, b3);
                mmah(acc[1][2 * p + 1], af[1], b2, b3);
            }
        }
    }

    // epilogue
#pragma unroll
    for (int ni = 0; ni < 8; ni++) {
        int j = bn + wn + ni * 8 + 2 * lr;
        float b0 = bias[j], b1 = bias[j + 1];
        if (qkv_mode) {
            int plane = j / 768, pc = j - plane * 768;
            __half* dst = (plane == 0) ? g_q : (plane == 1) ? g_k : g_v;
            float sc = (plane == 0) ? SCALE_Q : 1.f;
#pragma unroll
            for (int mi = 0; mi < 2; mi++) {
                int t = bm + wm + mi * 16 + lq;
#pragma unroll
                for (int hh = 0; hh < 2; hh++) {
                    int tt = t + 8 * hh;
                    float v0 = (acc[mi][ni][2 * hh + 0] + b0) * sc;
                    float v1 = (acc[mi][ni][2 * hh + 1] + b1) * sc;
                    *(unsigned*)(dst + (size_t)tt * EMB_ + pc) = packh(v0, v1);
                }
            }
        } else {
#pragma unroll
            for (int mi = 0; mi < 2; mi++) {
                int t = bm + wm + mi * 16 + lq;
                *(float2*)(Cf + (size_t)t * EMB_ + j) =
                    make_float2(acc[mi][ni][0] + b0, acc[mi][ni][1] + b1);
                *(float2*)(Cf + (size_t)(t + 8) * EMB_ + j) =
                    make_float2(acc[mi][ni][2] + b0, acc[mi][ni][3] + b1);
            }
        }
    }
}

// -------- attention: fp16 FA2, warp-private 32 rows, trans-LDSM V -----------
#define AQ   128
#define AKT  64                             // tokens per iter
#define LQ32 52                             // 48 data + 4 pad
#define LK32 52
#define LV32 52                             // V now row-major [token][d], like K
#define OFFK 6656                           // sQ = 128*52
#define OFFV (OFFK + 2 * AKT * LK32)        // 13312
#define ATTW (OFFV + 2 * AKT * LV32)        // 19968 w (79872 B)
#define NIT (SEQ / AKT)                     // 32

__device__ __forceinline__ void attn_issue(
    uint32_t smb, const __half* __restrict__ Kg, const __half* __restrict__ Vg,
    int tid, int it)
{
    const int base = it * AKT;
    const int buf = it & 1;
    const uint32_t kb = smb + (uint32_t)(OFFK + buf * (AKT * LK32)) * 4u;
    const uint32_t vb = smb + (uint32_t)(OFFV + buf * (AKT * LV32)) * 4u;
#pragma unroll
    for (int i = 0; i < 12; i++) {          // K,V: each 64 rows x 12 x 16B
        int id = tid + 128 * i;
        if (id < 768) {
            int r = id / 12, c4 = id - r * 12;
            cpa16(kb + (uint32_t)(r * LK32 + c4 * 4) * 4u,
                  Kg + (size_t)(base + r) * EMB_ + c4 * 8);
        } else {
            int id2 = id - 768;
            int r = id2 / 12, c4 = id2 - r * 12;
            cpa16(vb + (uint32_t)(r * LV32 + c4 * 4) * 4u,
                  Vg + (size_t)(base + r) * EMB_ + c4 * 8);
        }
    }
    CP_COMMIT();
}

__global__ __launch_bounds__(128, 2) void attn4() {
    extern __shared__ unsigned smw[];
    const uint32_t smb = (uint32_t)__cvta_generic_to_shared(smw);

    const int bh = blockIdx.y;
    const int qb = blockIdx.x * AQ;
    const int b = bh >> 3, h = bh & 7;
    const int tid = threadIdx.x, w = tid >> 5, lane = tid & 31;
    const int lq = lane >> 2, lr = lane & 3;
    const int wr = w * 32;                  // warp-private row base

    // per-lane LDSM offsets (words)
    const uint32_t offAq = ((lane & 7) + ((lane >> 3) & 1) * 8) * LQ32 + (lane >> 4) * 4;
    const uint32_t offBk = ((lane & 7) + ((lane >> 4) & 1) * 8) * LK32 + ((lane >> 3) & 1) * 4;
    // trans-B for V: row = token (k), col = d (n)
    const uint32_t offBv = ((lane & 7) + ((lane >> 3) & 1) * 8) * LV32 + ((lane >> 4) & 1) * 4;

    const __half* Qg = g_q + (size_t)(b * SEQ + qb) * EMB_ + h * HDIM;
    const __half* Kg = g_k + (size_t)(b * SEQ) * EMB_ + h * HDIM;
    const __half* Vg = g_v + (size_t)(b * SEQ) * EMB_ + h * HDIM;

    // prologue: Q tile + KV stage 0 (single commit group via attn_issue)
#pragma unroll
    for (int i = 0; i < 12; i++) {
        int id = tid + 128 * i, r = id / 12, c4 = id - r * 12;
        cpa16(smb + (uint32_t)(r * LQ32 + c4 * 4) * 4u,
              Qg + (size_t)r * EMB_ + c4 * 8);
    }
    attn_issue(smb, Kg, Vg, tid, 0);

    float o[2][12][4];
#pragma unroll
    for (int i = 0; i < 2; i++)
#pragma unroll
        for (int j = 0; j < 12; j++)
#pragma unroll
            for (int q = 0; q < 4; q++) o[i][j][q] = 0.f;
    float rs[2][2] = {{0.f, 0.f}, {0.f, 0.f}};

    for (int it = 0; it < NIT; ++it) {
        CP_WAIT(0);
        __syncthreads();
        if (it + 1 < NIT) attn_issue(smb, Kg, Vg, tid, it + 1);

        const uint32_t cKb = smb + (uint32_t)(OFFK + (it & 1) * (AKT * LK32)) * 4u;
        const uint32_t cVb = smb + (uint32_t)(OFFV + (it & 1) * (AKT * LV32)) * 4u;

        // S[32x64] per warp = Q @ K^T  (6 k16 steps over HDIM=96)
        float s[2][8][4];
#pragma unroll
        for (int i = 0; i < 2; i++)
#pragma unroll
            for (int j = 0; j < 8; j++)
#pragma unroll
                for (int q = 0; q < 4; q++) s[i][j][q] = 0.f;

#pragma unroll
        for (int kk = 0; kk < 6; kk++) {
            const uint32_t kw = kk * 8;
            unsigned af[2][4];
#pragma unroll
            for (int mi = 0; mi < 2; mi++)
                LDSM4(af[mi][0], af[mi][1], af[mi][2], af[mi][3],
                      smb + ((uint32_t)((wr + mi * 16) * LQ32) + kw + offAq) * 4u);
#pragma unroll
            for (int p = 0; p < 4; p++) {
                unsigned b0, b1, b2, b3;
                LDSM4(b0, b1, b2, b3,
                      cKb + ((uint32_t)(p * 16 * LK32) + kw + offBk) * 4u);
                mmah(s[0][2 * p], af[0], b0, b1);
                mmah(s[1][2 * p], af[1], b0, b1);
                mmah(s[0][2 * p + 1], af[0], b2, b3);
                mmah(s[1][2 * p + 1], af[1], b2, b3);
            }
        }

        // P = fp16(2^S), packed in-place as PV A-frag halves; f32 row sums
        unsigned ph[2][8][2];
#pragma unroll
        for (int mi = 0; mi < 2; mi++)
#pragma unroll
            for (int ni = 0; ni < 8; ni++) {
                unsigned u0 = packh(ex2f(s[mi][ni][0]), ex2f(s[mi][ni][1]));
                unsigned u1 = packh(ex2f(s[mi][ni][2]), ex2f(s[mi][ni][3]));
                ph[mi][ni][0] = u0;
                ph[mi][ni][1] = u1;
                float2 f0 = __half22float2(*(__half2*)&u0);
                float2 f1 = __half22float2(*(__half2*)&u1);
                rs[mi][0] += f0.x + f0.y;
                rs[mi][1] += f1.x + f1.y;
            }

        // O += P @ V : A-frags ARE the packed c-frags; V B-frags via trans-LDSM
#pragma unroll
        for (int j = 0; j < 4; j++) {       // k16 steps over 64 tokens
            unsigned af[2][4];
#pragma unroll
            for (int mi = 0; mi < 2; mi++) {
                af[mi][0] = ph[mi][2 * j][0];
                af[mi][1] = ph[mi][2 * j][1];
                af[mi][2] = ph[mi][2 * j + 1][0];
                af[mi][3] = ph[mi][2 * j + 1][1];
            }
#pragma unroll
            for (int p = 0; p < 6; p++) {   // n16 groups over 96 d
                unsigned b0, b1, b2, b3;
                LDSM4T(b0, b1, b2, b3,
                       cVb + ((uint32_t)(j * 16 * LV32) + p * 8 + offBv) * 4u);
                mmah(o[0][2 * p], af[0], b0, b1);
                mmah(o[1][2 * p], af[1], b0, b1);
                mmah(o[0][2 * p + 1], af[0], b2, b3);
                mmah(o[1][2 * p + 1], af[1], b2, b3);
            }
        }
    }

    // quad-reduce row sums (cols partitioned over lr within each quad)
#pragma unroll
    for (int mi = 0; mi < 2; mi++)
#pragma unroll
        for (int half = 0; half < 2; half++) {
            float v = rs[mi][half];
            v += __shfl_xor_sync(0xffffffffu, v, 1);
            v += __shfl_xor_sync(0xffffffffu, v, 2);
            rs[mi][half] = v;
        }

    // normalize, write ctx fp16
#pragma unroll
    for (int mi = 0; mi < 2; mi++) {
        int r0 = wr + mi * 16 + lq;
        float inv0 = 1.f / rs[mi][0];
        float inv1 = 1.f / rs[mi][1];
        size_t t0 = (size_t)(b * SEQ + qb + r0) * EMB_ + h * HDIM;
        size_t t1 = (size_t)(b * SEQ + qb + r0 + 8) * EMB_ + h * HDIM;
#pragma unroll
        for (int ni = 0; ni < 12; ni++) {
            int col = ni * 8 + 2 * lr;
            *(unsigned*)(g_ctx + t0 + col) = packh(o[mi][ni][0] * inv0,
                                                   o[mi][ni][1] * inv0);
            *(unsigned*)(g_ctx + t1 + col) = packh(o[mi][ni][2] * inv1,
                                                   o[mi][ni][3] * inv1);
        }
    }
}

// ---------------- launch -----------------------------------------------------
extern "C" void kernel_launch(void* const* d_in, const int* in_sizes, int n_in,
                              void* d_out, int out_size) {
    const float* x     = (const float*)d_in[0];
    const float* Wqkv  = (const float*)d_in[1];
    const float* bqkv  = (const float*)d_in[2];
    const float* Wproj = (const float*)d_in[3];
    const float* bproj = (const float*)d_in[4];
    float* out = (float*)d_out;

    void *pxh, *pw1, *pb1, *pw2, *pctx;
    cudaGetSymbolAddress(&pxh, g_xh);
    cudaGetSymbolAddress(&pw1, g_w1);
    cudaGetSymbolAddress(&pb1, g_b1);
    cudaGetSymbolAddress(&pw2, g_w2);
    cudaGetSymbolAddress(&pctx, g_ctx);

    const int gemm_smem = STG * STW * 4;   // 110592 B -> 2 CTAs/SM (16 warps)
    const int attn_smem = ATTW * 4;        // 79872 B  -> 2 CTAs/SM
    cudaFuncSetAttribute(gemm_h, cudaFuncAttributeMaxDynamicSharedMemorySize, gemm_smem);
    cudaFuncSetAttribute(attn4, cudaFuncAttributeMaxDynamicSharedMemorySize, attn_smem);

    // 0) prep: fp16 convert x; smem-transpose weight permutes (+bias fold)
    cvth_k<<<(TOK * EMB_ / 4 + 255) / 256, 256>>>(
        (const float4*)x, (__half2*)pxh, TOK * EMB_ / 4);
    permw_t<<<dim3(NQKV / 32, EMB_ / 32), dim3(32, 8)>>>(Wqkv, bqkv);
    transw2_t<<<dim3(EMB_ / 32, EMB_ / 32), dim3(32, 8)>>>(Wproj);

    // 1) qkv = x @ Wqkv'^T + bqkv' -> q (scaled), k, v planes (all row-major)
    gemm_h<<<dim3(NQKV / BN, TOK / BM), 256, gemm_smem>>>(
        (const __half*)pxh, (const __half*)pw1, (const float*)pb1, nullptr, 1);

    // 2) attention -> ctx (fp16)
    attn4<<<dim3(SEQ / AQ, 32), 128, attn_smem>>>();

    // 3) out = ctx @ Wproj^T + bproj (fp32 out)
    gemm_h<<<dim3(EMB_ / BN, TOK / BM), 256, gemm_smem>>>(
        (const __half*)pctx, (const __half*)pw2, bproj, out, 0);
}